// round 7
// baseline (speedup 1.0000x reference)
#include <cuda_runtime.h>
#include <cstdint>
#include <cmath>

#define EPS_F 1e-8f
#define TAU_CROSS 1e-4f

// ---------------- scratch (__device__ globals; no allocation allowed) ----------------
__device__ float g_proc[16777216];             // [64][512][512] gathered top-512 rows
__device__ float g_rn2[32768];                 // [64][512] 1/||proc row||
__device__ unsigned long long g_t2[196608];    // [48*512][4 ct][2] per-tile top-2 keys
__device__ unsigned long long g_best[24576];   // [48][512] winning key (low32 = 0xFFFFFFFF-m)
__device__ unsigned long long g_rlist[24576];  // flagged rows: n<<32|m1<<16|m2
__device__ int g_rcnt[48];

__device__ __forceinline__ unsigned int fsort(float f) {
    unsigned int u = __float_as_uint(f);
    return u ^ ((unsigned int)((int)u >> 31) | 0x80000000u);
}
__device__ __forceinline__ float finv(unsigned int u) {
    return __uint_as_float((u & 0x80000000u) ? (u ^ 0x80000000u) : ~u);
}
__device__ __forceinline__ void fma2(unsigned long long &c, unsigned long long a, unsigned long long b) {
    asm volatile("fma.rn.f32x2 %0, %1, %2, %0;" : "+l"(c) : "l"(a), "l"(b));
}
__device__ __forceinline__ unsigned long long dup2(float x) {
    unsigned long long r;
    asm("mov.b64 %0, {%1, %1};" : "=l"(r) : "f"(x));
    return r;
}
__device__ __forceinline__ void top2_upd(unsigned long long &b1, unsigned long long &b2,
                                         unsigned long long k) {
    if (k > b1) { b2 = b1; b1 = k; }
    else if (k > b2) b2 = k;
}
__device__ __forceinline__ void top2_merge(unsigned long long &b1, unsigned long long &b2,
                                           unsigned long long q1, unsigned long long q2) {
    unsigned long long hi = b1 > q1 ? b1 : q1;
    unsigned long long lo = b1 > q1 ? q1 : b1;
    unsigned long long m2 = b2 > q2 ? b2 : q2;
    b1 = hi;
    b2 = lo > m2 ? lo : m2;
}

// ---------------- K init ----------------
__global__ void k_init() {
    int i = blockIdx.x * blockDim.x + threadIdx.x;
    if (i < 48) g_rcnt[i] = 0;
}

// ---------------- K0: scores -> fp32-quantized softmax weights -> top-512 -> gather+norms ----
__global__ void __launch_bounds__(1024) k_scores(const float* __restrict__ clips,
                                                 const float* __restrict__ W) {
    __shared__ float sW[512];
    __shared__ float sS[1024];
    __shared__ float redf[1024];
    __shared__ double redd[1024];
    __shared__ unsigned long long keys[1024];
    __shared__ int sidx[512];
    __shared__ float snorm[512];
    int tid = threadIdx.x;
    int cb = blockIdx.x;
    const float* x = clips + (size_t)cb * (1024 * 512);
    if (tid < 512) { sW[tid] = W[tid]; snorm[tid] = 0.f; }
    __syncthreads();

    int warp = tid >> 5, lane = tid & 31;
    for (int tt = 0; tt < 32; tt++) {
        int token = (warp << 5) + tt;
        const float* r = x + (size_t)token * 512;
        float s = 0.f;
#pragma unroll 4
        for (int d = lane; d < 512; d += 32) s += r[d] * sW[d];
#pragma unroll
        for (int o = 16; o; o >>= 1) s += __shfl_xor_sync(0xFFFFFFFFu, s, o);
        if (lane == 0) sS[token] = s;
    }
    __syncthreads();

    // exact fp32 max
    redf[tid] = sS[tid];
    __syncthreads();
    for (int sft = 512; sft; sft >>= 1) {
        if (tid < sft) redf[tid] = fmaxf(redf[tid], redf[tid + sft]);
        __syncthreads();
    }
    float smax = redf[0];

    // fp64 exp + fp64 sum (order-independent common divisor)
    double e = exp((double)sS[tid] - (double)smax);
    redd[tid] = e;
    __syncthreads();
    for (int sft = 512; sft; sft >>= 1) {
        if (tid < sft) redd[tid] += redd[tid + sft];
        __syncthreads();
    }
    double esum = redd[0];

    float w32 = (float)(e / esum);  // fp32 weight XLA ranks by
    keys[tid] = ((unsigned long long)fsort(w32) << 32) |
                (unsigned long long)(tid ^ 0x3FF);  // tie -> lower index first
    __syncthreads();

    // bitonic sort, descending (weight desc, index asc on bitwise ties)
    for (int ks = 2; ks <= 1024; ks <<= 1)
        for (int j = ks >> 1; j > 0; j >>= 1) {
            __syncthreads();
            int i = tid, ixj = i ^ j;
            if (ixj > i) {
                unsigned long long a = keys[i], b = keys[ixj];
                bool sw = ((i & ks) == 0) ? (a < b) : (a > b);
                if (sw) { keys[i] = b; keys[ixj] = a; }
            }
        }
    __syncthreads();
    if (tid < 512) sidx[tid] = ((int)(keys[tid] & 0x3FFu)) ^ 0x3FF;
    __syncthreads();

    // gather top-512 rows + fused row sum-of-squares
    float* dst = g_proc + (size_t)cb * (512 * 512);
    int half = tid >> 9;
    int d = tid & 511;
    for (int base = 0; base < 512; base += 2) {
        int j = base + half;
        float v = x[(size_t)sidx[j] * 512 + d];
        dst[(size_t)j * 512 + d] = v;
        float p = v * v;
#pragma unroll
        for (int o = 16; o; o >>= 1) p += __shfl_xor_sync(0xFFFFFFFFu, p, o);
        if (lane == 0) atomicAdd(&snorm[j], p);
    }
    __syncthreads();
    if (tid < 512) g_rn2[(size_t)cb * 512 + tid] = 1.0f / sqrtf(snorm[tid]);
}

// ---------------- K2: persistent cross-pair GEMM + fused per-tile TOP-2 ----------------
// 296 persistent blocks; 768 tiles = 48 pairs * 4x4; 128x128 tile, 8x8/thread.
// A stored plain (dedup'd) in smem; (a,a) pairs built in registers; double-buffered,
// one __syncthreads per k-chunk.
__global__ void __launch_bounds__(256, 2) k_cross() {
    __shared__ __align__(16) float Ast[2][8][132];  // [buf][kk][row], pad 4
    __shared__ __align__(16) float Bst[2][8][132];  // [buf][kk][col], pad 4
    __shared__ float sRn[128];

    int tid = threadIdx.x;
    int tx = tid & 15, ty = tid >> 4;
    int lr = tid >> 1;
    int lk = (tid & 1) << 2;

    for (int tile = blockIdx.x; tile < 768; tile += 296) {
        int pair = tile >> 4;
        int rt = (tile >> 2) & 3;
        int ct = tile & 3;
        const float* x1 = g_proc + (size_t)pair * 262144 + (size_t)rt * 65536;
        const float* x2 = g_proc + (size_t)(pair + 16) * 262144 + (size_t)ct * 65536;

        __syncthreads();  // protect sRn (+smem) reuse across tiles
        if (tid < 128) sRn[tid] = g_rn2[(size_t)(pair + 16) * 512 + ct * 128 + tid];

        unsigned long long acc[8][4];
#pragma unroll
        for (int i = 0; i < 8; i++)
#pragma unroll
            for (int j = 0; j < 4; j++) acc[i][j] = 0ull;

        const float* pa = x1 + (size_t)lr * 512 + lk;
        const float* pb = x2 + (size_t)lr * 512 + lk;

        // prologue: chunk 0 -> buf 0
        float4 va = *(const float4*)(pa);
        float4 vb = *(const float4*)(pb);
        Ast[0][lk + 0][lr] = va.x; Ast[0][lk + 1][lr] = va.y;
        Ast[0][lk + 2][lr] = va.z; Ast[0][lk + 3][lr] = va.w;
        Bst[0][lk + 0][lr] = vb.x; Bst[0][lk + 1][lr] = vb.y;
        Bst[0][lk + 2][lr] = vb.z; Bst[0][lk + 3][lr] = vb.w;
        __syncthreads();

        for (int c = 0; c < 64; c++) {
            int cur = c & 1;
            if (c < 63) {  // prefetch next chunk while FMAs run
                va = *(const float4*)(pa + (c + 1) * 8);
                vb = *(const float4*)(pb + (c + 1) * 8);
            }
#pragma unroll
            for (int kk = 0; kk < 8; kk++) {
                float4 af0 = *(const float4*)(&Ast[cur][kk][8 * ty]);
                float4 af1 = *(const float4*)(&Ast[cur][kk][8 * ty + 4]);
                ulonglong2 bq0 = *(const ulonglong2*)(&Bst[cur][kk][8 * tx]);
                ulonglong2 bq1 = *(const ulonglong2*)(&Bst[cur][kk][8 * tx + 4]);
                unsigned long long b[4] = {bq0.x, bq0.y, bq1.x, bq1.y};
                unsigned long long a[8];
                a[0] = dup2(af0.x); a[1] = dup2(af0.y);
                a[2] = dup2(af0.z); a[3] = dup2(af0.w);
                a[4] = dup2(af1.x); a[5] = dup2(af1.y);
                a[6] = dup2(af1.z); a[7] = dup2(af1.w);
#pragma unroll
                for (int i = 0; i < 8; i++)
#pragma unroll
                    for (int j = 0; j < 4; j++) fma2(acc[i][j], a[i], b[j]);
            }
            if (c < 63) {
                int nb = cur ^ 1;
                Ast[nb][lk + 0][lr] = va.x; Ast[nb][lk + 1][lr] = va.y;
                Ast[nb][lk + 2][lr] = va.z; Ast[nb][lk + 3][lr] = va.w;
                Bst[nb][lk + 0][lr] = vb.x; Bst[nb][lk + 1][lr] = vb.y;
                Bst[nb][lk + 2][lr] = vb.z; Bst[nb][lk + 3][lr] = vb.w;
            }
            __syncthreads();
        }

        // epilogue: per-row TOP-2 within this 128-col tile
#pragma unroll
        for (int i = 0; i < 8; i++) {
            int n = rt * 128 + ty * 8 + i;
            unsigned long long b1 = 0ull, b2 = 0ull;
#pragma unroll
            for (int j = 0; j < 4; j++) {
                float lo, hi;
                asm volatile("mov.b64 {%0, %1}, %2;" : "=f"(lo), "=f"(hi) : "l"(acc[i][j]));
                int m0 = tx * 8 + j * 2;
                float v0 = lo * sRn[m0];
                float v1 = hi * sRn[m0 + 1];
                top2_upd(b1, b2, ((unsigned long long)fsort(v0) << 32) |
                                 (unsigned long long)(0xFFFFFFFFu - (unsigned)(ct * 128 + m0)));
                top2_upd(b1, b2, ((unsigned long long)fsort(v1) << 32) |
                                 (unsigned long long)(0xFFFFFFFFu - (unsigned)(ct * 128 + m0 + 1)));
            }
#pragma unroll
            for (int o = 8; o; o >>= 1) {
                unsigned long long q1 = __shfl_xor_sync(0xFFFFFFFFu, b1, o, 16);
                unsigned long long q2 = __shfl_xor_sync(0xFFFFFFFFu, b2, o, 16);
                top2_merge(b1, b2, q1, q2);
            }
            if (tx == 0) {
                size_t base = (((size_t)pair * 512 + n) * 4 + ct) * 2;
                g_t2[base] = b1;
                g_t2[base + 1] = b2;
            }
        }
    }
}

// ---------------- K2b: global top-2 per row; flag near-ties ----------------
__global__ void k_select() {
    int row = blockIdx.x * 256 + threadIdx.x;  // < 24576
    int pair = row >> 9;
    unsigned long long b1 = 0ull, b2 = 0ull;
#pragma unroll
    for (int ct = 0; ct < 4; ct++) {
        size_t base = ((size_t)row * 4 + ct) * 2;
        top2_merge(b1, b2, g_t2[base], g_t2[base + 1]);
    }
    g_best[row] = b1;
    float v1 = finv((unsigned)(b1 >> 32));
    float v2 = finv((unsigned)(b2 >> 32));
    if (v1 - v2 < TAU_CROSS) {
        int n = row & 511;
        unsigned m1 = ~(unsigned)b1 & 0xFFFFu;
        unsigned m2 = ~(unsigned)b2 & 0xFFFFu;
        int slot = atomicAdd(&g_rcnt[pair], 1);
        g_rlist[(size_t)pair * 512 + slot] =
            ((unsigned long long)n << 32) | ((unsigned long long)m1 << 16) | m2;
    }
}

// ---------------- K2c: fp64 rescue of flagged rows (exact argmax) ----------------
__global__ void __launch_bounds__(256) k_rescue() {
    int pair = blockIdx.x;
    int w = threadIdx.x >> 5, lane = threadIdx.x & 31;
    int cnt = g_rcnt[pair];
    for (int e = w; e < cnt; e += 8) {
        unsigned long long ent = g_rlist[(size_t)pair * 512 + e];
        int n = (int)(ent >> 32);
        int m1 = (int)((ent >> 16) & 0xFFFFu);
        int m2 = (int)(ent & 0xFFFFu);
        const float* a = g_proc + (size_t)pair * 262144 + (size_t)n * 512;
        const float* p1 = g_proc + (size_t)(pair + 16) * 262144 + (size_t)m1 * 512;
        const float* p2 = g_proc + (size_t)(pair + 16) * 262144 + (size_t)m2 * 512;
        double d1 = 0, d2 = 0, q1 = 0, q2 = 0;
        for (int d = lane; d < 512; d += 32) {
            double av = a[d], v1 = p1[d], v2 = p2[d];
            d1 += av * v1; q1 += v1 * v1;
            d2 += av * v2; q2 += v2 * v2;
        }
#pragma unroll
        for (int o = 16; o; o >>= 1) {
            d1 += __shfl_xor_sync(0xFFFFFFFFu, d1, o);
            d2 += __shfl_xor_sync(0xFFFFFFFFu, d2, o);
            q1 += __shfl_xor_sync(0xFFFFFFFFu, q1, o);
            q2 += __shfl_xor_sync(0xFFFFFFFFu, q2, o);
        }
        if (lane == 0) {
            double s1 = d1 * sqrt(q2);
            double s2 = d2 * sqrt(q1);
            int m;
            if (s1 > s2) m = m1;
            else if (s2 > s1) m = m2;
            else m = m1 < m2 ? m1 : m2;
            g_best[(size_t)pair * 512 + n] =
                (0x8000000000000000ull) | (unsigned long long)(0xFFFFFFFFu - (unsigned)m);
        }
    }
}

// ---------------- K3: intra merge (row-0 sims, top-256 set, mean) + output ----------------
__global__ void __launch_bounds__(512) k_intra(float* __restrict__ out) {
    int p = blockIdx.x;
    const float* x1 = g_proc + (size_t)p * 262144;
    const float* x2 = g_proc + (size_t)(p + 16) * 262144;
    __shared__ float pm0[512];
    __shared__ float cdot[512];
    __shared__ float cn[512];
    __shared__ int stop[512];
    __shared__ unsigned long long keys[512];
    int tid = threadIdx.x;

    stop[tid] = (int)(0xFFFFFFFFu - (unsigned)g_best[(size_t)p * 512 + tid]);
    __syncthreads();
    int t0 = stop[0];
    pm0[tid] = 0.5f * (x1[(size_t)t0 * 512 + tid] + x2[(size_t)t0 * 512 + tid]);
    __syncthreads();

    int warp = tid >> 5, lane = tid & 31;
    for (int j = warp; j < 512; j += 16) {
        const float* r1 = x1 + (size_t)j * 512;
        const float* r2 = x2 + (size_t)j * 512;
        float sd = 0.f, sn = 0.f;
#pragma unroll 4
        for (int d = lane; d < 512; d += 32) {
            float v = 0.5f * (r1[d] + r2[d]);
            sd += pm0[d] * v;
            sn += v * v;
        }
#pragma unroll
        for (int o = 16; o; o >>= 1) {
            sd += __shfl_xor_sync(0xFFFFFFFFu, sd, o);
            sn += __shfl_xor_sync(0xFFFFFFFFu, sn, o);
        }
        if (lane == 0) { cdot[j] = sd; cn[j] = sqrtf(sn); }
    }
    __syncthreads();

    float n0 = cn[t0];
    {
        int t = stop[tid];
        float v = cdot[t] / fmaxf(n0 * cn[t], EPS_F);
        keys[tid] = ((unsigned long long)fsort(v) << 32) |
                    (unsigned long long)(0xFFFFFFFFu - (unsigned)tid);
    }

    for (int ks = 2; ks <= 512; ks <<= 1)
        for (int j = ks >> 1; j > 0; j >>= 1) {
            __syncthreads();
            int i = tid, ixj = i ^ j;
            if (ixj > i) {
                unsigned long long a = keys[i], b = keys[ixj];
                bool sw = ((i & ks) == 0) ? (a < b) : (a > b);
                if (sw) { keys[i] = b; keys[ixj] = a; }
            }
        }
    __syncthreads();

    float accv = 0.f;
    for (int s = 0; s < 256; s++) {
        int mm = (int)(0xFFFFFFFFu - (unsigned)keys[s]);
        int t = stop[mm];
        accv += x1[(size_t)t * 512 + tid] + x2[(size_t)t * 512 + tid];
    }
    out[(size_t)p * 512 + tid] = accv * (0.5f / 256.0f);
}

// ---------------- launch ----------------
extern "C" void kernel_launch(void* const* d_in, const int* in_sizes, int n_in,
                              void* d_out, int out_size) {
    const float* clips = (const float*)d_in[0];
    const float* W     = (const float*)d_in[1];
    (void)in_sizes; (void)n_in; (void)out_size;

    k_init<<<1, 64>>>();
    k_scores<<<64, 1024>>>(clips, W);
    k_cross<<<296, 256>>>();
    k_select<<<96, 256>>>();
    k_rescue<<<48, 256>>>();
    k_intra<<<48, 512>>>((float*)d_out);
}

// round 11
// speedup vs baseline: 1.1977x; 1.1977x over previous
#include <cuda_runtime.h>
#include <cuda_bf16.h>
#include <cstdint>
#include <cmath>

#define EPS_F 1e-8f
#define TAU_CROSS 1e-4f

// ---------------- scratch (__device__ globals; no allocation allowed) ----------------
__device__ float g_proc[16777216];             // [64][512][512] gathered top-512 rows (fp32)
__device__ __nv_bfloat16 g_bhi[16777216];      // bf16 hi part of g_proc
__device__ __nv_bfloat16 g_blo[16777216];      // bf16 lo part (v - hi)
__device__ float g_rn2[32768];                 // [64][512] 1/||proc row||
__device__ unsigned long long g_t2[196608];    // [48*512][4 ct][2] per-tile top-2 keys
__device__ unsigned long long g_best[24576];   // winning key (low32 = 0xFFFFFFFF-m)
__device__ unsigned long long g_rlist[24576];  // flagged rows: n<<32|m1<<16|m2
__device__ int g_rcnt[48];

// ---------------- helpers ----------------
__device__ __forceinline__ unsigned int fsort(float f) {
    unsigned int u = __float_as_uint(f);
    return u ^ ((unsigned int)((int)u >> 31) | 0x80000000u);
}
__device__ __forceinline__ float finv(unsigned int u) {
    return __uint_as_float((u & 0x80000000u) ? (u ^ 0x80000000u) : ~u);
}
__device__ __forceinline__ void top2_upd(unsigned long long &b1, unsigned long long &b2,
                                         unsigned long long k) {
    if (k > b1) { b2 = b1; b1 = k; }
    else if (k > b2) b2 = k;
}
__device__ __forceinline__ void top2_merge(unsigned long long &b1, unsigned long long &b2,
                                           unsigned long long q1, unsigned long long q2) {
    unsigned long long hi = b1 > q1 ? b1 : q1;
    unsigned long long lo = b1 > q1 ? q1 : b1;
    unsigned long long m2 = b2 > q2 ? b2 : q2;
    b1 = hi;
    b2 = lo > m2 ? lo : m2;
}
__device__ __forceinline__ uint32_t smem_to_u32(const void* p) {
    uint32_t a;
    asm("{ .reg .u64 t; cvta.to.shared.u64 t, %1; cvt.u32.u64 %0, t; }" : "=r"(a) : "l"(p));
    return a;
}
__device__ __forceinline__ void cp16(uint32_t s, const void* g) {
    asm volatile("cp.async.cg.shared.global [%0], [%1], 16;" :: "r"(s), "l"(g));
}
#define CP_COMMIT() asm volatile("cp.async.commit_group;" ::: "memory")
#define CP_WAIT(N) asm volatile("cp.async.wait_group %0;" :: "n"(N) : "memory")

__device__ __forceinline__ void ldm_x4(uint32_t &r0, uint32_t &r1, uint32_t &r2, uint32_t &r3,
                                       uint32_t a) {
    asm volatile("ldmatrix.sync.aligned.m8n8.x4.shared.b16 {%0,%1,%2,%3}, [%4];"
                 : "=r"(r0), "=r"(r1), "=r"(r2), "=r"(r3) : "r"(a));
}
__device__ __forceinline__ void ldm_x2(uint32_t &r0, uint32_t &r1, uint32_t a) {
    asm volatile("ldmatrix.sync.aligned.m8n8.x2.shared.b16 {%0,%1}, [%2];"
                 : "=r"(r0), "=r"(r1) : "r"(a));
}
__device__ __forceinline__ void mma_bf16(float* d, const uint32_t* a, const uint32_t* b) {
    asm volatile("mma.sync.aligned.m16n8k16.row.col.f32.bf16.bf16.f32 "
                 "{%0,%1,%2,%3}, {%4,%5,%6,%7}, {%8,%9}, {%0,%1,%2,%3};"
                 : "+f"(d[0]), "+f"(d[1]), "+f"(d[2]), "+f"(d[3])
                 : "r"(a[0]), "r"(a[1]), "r"(a[2]), "r"(a[3]), "r"(b[0]), "r"(b[1]));
}

// ---------------- K init ----------------
__global__ void k_init() {
    int i = blockIdx.x * blockDim.x + threadIdx.x;
    if (i < 48) g_rcnt[i] = 0;
}

// ---------------- K0: scores -> fp32-quantized softmax weights -> top-512 -> gather ----
__global__ void __launch_bounds__(1024) k_scores(const float* __restrict__ clips,
                                                 const float* __restrict__ W) {
    __shared__ float sW[512];
    __shared__ float sS[1024];
    __shared__ float redf[1024];
    __shared__ double redd[1024];
    __shared__ unsigned long long keys[1024];
    __shared__ int sidx[512];
    __shared__ float snorm[512];
    int tid = threadIdx.x;
    int cb = blockIdx.x;
    const float* x = clips + (size_t)cb * (1024 * 512);
    if (tid < 512) { sW[tid] = W[tid]; snorm[tid] = 0.f; }
    __syncthreads();

    int warp = tid >> 5, lane = tid & 31;
    for (int tt = 0; tt < 32; tt++) {
        int token = (warp << 5) + tt;
        const float* r = x + (size_t)token * 512;
        float s = 0.f;
#pragma unroll 4
        for (int d = lane; d < 512; d += 32) s += r[d] * sW[d];
#pragma unroll
        for (int o = 16; o; o >>= 1) s += __shfl_xor_sync(0xFFFFFFFFu, s, o);
        if (lane == 0) sS[token] = s;
    }
    __syncthreads();

    redf[tid] = sS[tid];
    __syncthreads();
    for (int sft = 512; sft; sft >>= 1) {
        if (tid < sft) redf[tid] = fmaxf(redf[tid], redf[tid + sft]);
        __syncthreads();
    }
    float smax = redf[0];

    double e = exp((double)sS[tid] - (double)smax);
    redd[tid] = e;
    __syncthreads();
    for (int sft = 512; sft; sft >>= 1) {
        if (tid < sft) redd[tid] += redd[tid + sft];
        __syncthreads();
    }
    double esum = redd[0];

    float w32 = (float)(e / esum);  // fp32 weight XLA ranks by
    keys[tid] = ((unsigned long long)fsort(w32) << 32) |
                (unsigned long long)(tid ^ 0x3FF);  // tie -> lower index first
    __syncthreads();

    for (int ks = 2; ks <= 1024; ks <<= 1)
        for (int j = ks >> 1; j > 0; j >>= 1) {
            __syncthreads();
            int i = tid, ixj = i ^ j;
            if (ixj > i) {
                unsigned long long a = keys[i], b = keys[ixj];
                bool sw = ((i & ks) == 0) ? (a < b) : (a > b);
                if (sw) { keys[i] = b; keys[ixj] = a; }
            }
        }
    __syncthreads();
    if (tid < 512) sidx[tid] = ((int)(keys[tid] & 0x3FFu)) ^ 0x3FF;
    __syncthreads();

    // gather + row sumsq + bf16 hi/lo split
    float* dst = g_proc + (size_t)cb * 262144;
    __nv_bfloat16* dh = g_bhi + (size_t)cb * 262144;
    __nv_bfloat16* dl = g_blo + (size_t)cb * 262144;
    int half = tid >> 9;
    int d = tid & 511;
    for (int base = 0; base < 512; base += 2) {
        int j = base + half;
        float v = x[(size_t)sidx[j] * 512 + d];
        size_t o = (size_t)j * 512 + d;
        dst[o] = v;
        __nv_bfloat16 h = __float2bfloat16(v);
        dh[o] = h;
        dl[o] = __float2bfloat16(v - __bfloat162float(h));
        float p = v * v;
#pragma unroll
        for (int oo = 16; oo; oo >>= 1) p += __shfl_xor_sync(0xFFFFFFFFu, p, oo);
        if (lane == 0) atomicAdd(&snorm[j], p);
    }
    __syncthreads();
    if (tid < 512) g_rn2[(size_t)cb * 512 + tid] = 1.0f / sqrtf(snorm[tid]);
}

// ---------------- K2: mma.sync split-bf16 GEMM (hh+hl+lh) + fused per-tile TOP-2 ------
// 768 CTAs = 48 pairs * 4 rt * 4 ct; 128x128 tile; 8 warps, warp tile 64x32; K chunks of 32.
// SINGLE-stage staging (fits 48KB default dynamic smem; no cudaFuncSetAttribute needed).
#define ROWB 80
#define MAT_SZ 10240                 // 128 rows * 80 B
#define STAGE_BYTES 40960            // 4 matrices
#define OFF_AHI 0
#define OFF_ALO 10240
#define OFF_BHI 20480
#define OFF_BLO 30720
#define SM_T2 40960                  // 128 rows * 4 nwarps * 2 keys * 8 B = 8192
#define SM_TOT 49152                 // == 48KB default limit

__global__ void __launch_bounds__(256) k_cross_mma() {
    extern __shared__ __align__(16) char smem[];
    uint32_t sb = smem_to_u32(smem);
    int tid = threadIdx.x;
    int lane = tid & 31, wid = tid >> 5;
    int tile = blockIdx.x;
    int pair = tile >> 4;
    int rt = (tile >> 2) & 3;
    int ct = tile & 3;

    size_t abase = ((size_t)pair * 512 + rt * 128) * 512;        // x1 tile (A, rows n)
    size_t bbase = ((size_t)(pair + 16) * 512 + ct * 128) * 512; // x2 tile (B, cols m)

    // cp.async geometry: thread t covers (row = t>>1, quads (t&1)*2 + {0,1}) of each matrix
    int lrow = tid >> 1;
    int lq = (tid & 1) * 2;
    uint32_t sdst = lrow * ROWB + lq * 16;
    size_t ga = abase + (size_t)lrow * 512 + lq * 8;
    size_t gb = bbase + (size_t)lrow * 512 + lq * 8;

    // fragment geometry
    int wm = (wid & 1) * 64;
    int wn = (wid >> 1) * 32;
    uint32_t a_off = (uint32_t)((wm + (lane & 15)) * ROWB + ((lane & 16) ? 16 : 0));
    uint32_t b_off = (uint32_t)((wn + (lane & 7)) * ROWB + ((lane & 8) ? 16 : 0));

    float d[4][4][4];
#pragma unroll
    for (int i = 0; i < 4; i++)
#pragma unroll
        for (int j = 0; j < 4; j++)
#pragma unroll
            for (int r = 0; r < 4; r++) d[i][j][r] = 0.f;

    for (int c = 0; c < 16; c++) {
        // stage chunk c (single buffer)
        {
            uint32_t s0 = sb + sdst;
            size_t go = (size_t)c * 32;
            cp16(s0 + OFF_AHI, g_bhi + ga + go);
            cp16(s0 + OFF_AHI + 16, g_bhi + ga + go + 8);
            cp16(s0 + OFF_ALO, g_blo + ga + go);
            cp16(s0 + OFF_ALO + 16, g_blo + ga + go + 8);
            cp16(s0 + OFF_BHI, g_bhi + gb + go);
            cp16(s0 + OFF_BHI + 16, g_bhi + gb + go + 8);
            cp16(s0 + OFF_BLO, g_blo + gb + go);
            cp16(s0 + OFF_BLO + 16, g_blo + gb + go + 8);
            CP_COMMIT();
        }
        CP_WAIT(0);
        __syncthreads();
#pragma unroll
        for (int s = 0; s < 2; s++) {
            uint32_t ah[4][4], al[4][4], bh[4][2], bl[4][2];
#pragma unroll
            for (int i = 0; i < 4; i++) {
                ldm_x4(ah[i][0], ah[i][1], ah[i][2], ah[i][3],
                       sb + OFF_AHI + a_off + i * (16 * ROWB) + s * 32);
                ldm_x4(al[i][0], al[i][1], al[i][2], al[i][3],
                       sb + OFF_ALO + a_off + i * (16 * ROWB) + s * 32);
            }
#pragma unroll
            for (int j = 0; j < 4; j++) {
                ldm_x2(bh[j][0], bh[j][1], sb + OFF_BHI + b_off + j * (8 * ROWB) + s * 32);
                ldm_x2(bl[j][0], bl[j][1], sb + OFF_BLO + b_off + j * (8 * ROWB) + s * 32);
            }
#pragma unroll
            for (int i = 0; i < 4; i++)
#pragma unroll
                for (int j = 0; j < 4; j++) {
                    mma_bf16(d[i][j], ah[i], bh[j]);
                    mma_bf16(d[i][j], ah[i], bl[j]);
                    mma_bf16(d[i][j], al[i], bh[j]);
                }
        }
        __syncthreads();  // before next chunk overwrites the single stage
    }

    // epilogue: per-row TOP-2. D frag: c0=(r,c) c1=(r,c+1) c2=(r+8,c) c3=(r+8,c+1)
    // rn2 read straight from global (L2-hot; 8 values per thread)
    const float* gRn = g_rn2 + (size_t)(pair + 16) * 512 + ct * 128;
    unsigned long long* sT2 = (unsigned long long*)(smem + SM_T2);
#pragma unroll
    for (int i = 0; i < 4; i++)
#pragma unroll
        for (int hf = 0; hf < 2; hf++) {
            int row = wm + i * 16 + hf * 8 + (lane >> 2);
            unsigned long long b1 = 0ull, b2 = 0ull;
#pragma unroll
            for (int j = 0; j < 4; j++) {
                int col = wn + j * 8 + (lane & 3) * 2;
                float v0 = d[i][j][hf * 2 + 0] * __ldg(gRn + col);
                float v1 = d[i][j][hf * 2 + 1] * __ldg(gRn + col + 1);
                top2_upd(b1, b2, ((unsigned long long)fsort(v0) << 32) |
                                 (unsigned long long)(0xFFFFFFFFu - (unsigned)(ct * 128 + col)));
                top2_upd(b1, b2, ((unsigned long long)fsort(v1) << 32) |
                                 (unsigned long long)(0xFFFFFFFFu - (unsigned)(ct * 128 + col + 1)));
            }
#pragma unroll
            for (int o = 1; o <= 2; o <<= 1) {
                unsigned long long q1 = __shfl_xor_sync(0xFFFFFFFFu, b1, o);
                unsigned long long q2 = __shfl_xor_sync(0xFFFFFFFFu, b2, o);
                top2_merge(b1, b2, q1, q2);
            }
            if ((lane & 3) == 0) {
                sT2[(row * 4 + (wid >> 1)) * 2] = b1;
                sT2[(row * 4 + (wid >> 1)) * 2 + 1] = b2;
            }
        }
    __syncthreads();
    if (tid < 128) {
        unsigned long long b1 = 0ull, b2 = 0ull;
#pragma unroll
        for (int nw = 0; nw < 4; nw++)
            top2_merge(b1, b2, sT2[(tid * 4 + nw) * 2], sT2[(tid * 4 + nw) * 2 + 1]);
        size_t base = (((size_t)pair * 512 + rt * 128 + tid) * 4 + ct) * 2;
        g_t2[base] = b1;
        g_t2[base + 1] = b2;
    }
}

// ---------------- K2b: global top-2 per row; flag near-ties ----------------
__global__ void k_select() {
    int row = blockIdx.x * 256 + threadIdx.x;  // < 24576
    int pair = row >> 9;
    unsigned long long b1 = 0ull, b2 = 0ull;
#pragma unroll
    for (int ct = 0; ct < 4; ct++) {
        size_t base = ((size_t)row * 4 + ct) * 2;
        top2_merge(b1, b2, g_t2[base], g_t2[base + 1]);
    }
    g_best[row] = b1;
    float v1 = finv((unsigned)(b1 >> 32));
    float v2 = finv((unsigned)(b2 >> 32));
    if (v1 - v2 < TAU_CROSS) {
        int n = row & 511;
        unsigned m1 = ~(unsigned)b1 & 0xFFFFu;
        unsigned m2 = ~(unsigned)b2 & 0xFFFFu;
        int slot = atomicAdd(&g_rcnt[pair], 1);
        g_rlist[(size_t)pair * 512 + slot] =
            ((unsigned long long)n << 32) | ((unsigned long long)m1 << 16) | m2;
    }
}

// ---------------- K2c: fp64 rescue of flagged rows (exact argmax) ----------------
__global__ void __launch_bounds__(256) k_rescue() {
    int pair = blockIdx.x;
    int w = threadIdx.x >> 5, lane = threadIdx.x & 31;
    int cnt = g_rcnt[pair];
    for (int e = w; e < cnt; e += 8) {
        unsigned long long ent = g_rlist[(size_t)pair * 512 + e];
        int n = (int)(ent >> 32);
        int m1 = (int)((ent >> 16) & 0xFFFFu);
        int m2 = (int)(ent & 0xFFFFu);
        const float* a = g_proc + (size_t)pair * 262144 + (size_t)n * 512;
        const float* p1 = g_proc + (size_t)(pair + 16) * 262144 + (size_t)m1 * 512;
        const float* p2 = g_proc + (size_t)(pair + 16) * 262144 + (size_t)m2 * 512;
        double d1 = 0, d2 = 0, q1 = 0, q2 = 0;
        for (int d = lane; d < 512; d += 32) {
            double av = a[d], v1 = p1[d], v2 = p2[d];
            d1 += av * v1; q1 += v1 * v1;
            d2 += av * v2; q2 += v2 * v2;
        }
#pragma unroll
        for (int o = 16; o; o >>= 1) {
            d1 += __shfl_xor_sync(0xFFFFFFFFu, d1, o);
            d2 += __shfl_xor_sync(0xFFFFFFFFu, d2, o);
            q1 += __shfl_xor_sync(0xFFFFFFFFu, q1, o);
            q2 += __shfl_xor_sync(0xFFFFFFFFu, q2, o);
        }
        if (lane == 0) {
            double s1 = d1 * sqrt(q2);
            double s2 = d2 * sqrt(q1);
            int m;
            if (s1 > s2) m = m1;
            else if (s2 > s1) m = m2;
            else m = m1 < m2 ? m1 : m2;
            g_best[(size_t)pair * 512 + n] =
                (0x8000000000000000ull) | (unsigned long long)(0xFFFFFFFFu - (unsigned)m);
        }
    }
}

// ---------------- K3: intra merge (row-0 sims, top-256 set, mean) + output ----------------
__global__ void __launch_bounds__(512) k_intra(float* __restrict__ out) {
    int p = blockIdx.x;
    const float* x1 = g_proc + (size_t)p * 262144;
    const float* x2 = g_proc + (size_t)(p + 16) * 262144;
    __shared__ float pm0[512];
    __shared__ float cdot[512];
    __shared__ float cn[512];
    __shared__ int stop[512];
    __shared__ unsigned long long keys[512];
    int tid = threadIdx.x;

    stop[tid] = (int)(0xFFFFFFFFu - (unsigned)g_best[(size_t)p * 512 + tid]);
    __syncthreads();
    int t0 = stop[0];
    pm0[tid] = 0.5f * (x1[(size_t)t0 * 512 + tid] + x2[(size_t)t0 * 512 + tid]);
    __syncthreads();

    int warp = tid >> 5, lane = tid & 31;
    for (int j = warp; j < 512; j += 16) {
        const float* r1 = x1 + (size_t)j * 512;
        const float* r2 = x2 + (size_t)j * 512;
        float sd = 0.f, sn = 0.f;
#pragma unroll 4
        for (int d = lane; d < 512; d += 32) {
            float v = 0.5f * (r1[d] + r2[d]);
            sd += pm0[d] * v;
            sn += v * v;
        }
#pragma unroll
        for (int o = 16; o; o >>= 1) {
            sd += __shfl_xor_sync(0xFFFFFFFFu, sd, o);
            sn += __shfl_xor_sync(0xFFFFFFFFu, sn, o);
        }
        if (lane == 0) { cdot[j] = sd; cn[j] = sqrtf(sn); }
    }
    __syncthreads();

    float n0 = cn[t0];
    {
        int t = stop[tid];
        float v = cdot[t] / fmaxf(n0 * cn[t], EPS_F);
        keys[tid] = ((unsigned long long)fsort(v) << 32) |
                    (unsigned long long)(0xFFFFFFFFu - (unsigned)tid);
    }

    for (int ks = 2; ks <= 512; ks <<= 1)
        for (int j = ks >> 1; j > 0; j >>= 1) {
            __syncthreads();
            int i = tid, ixj = i ^ j;
            if (ixj > i) {
                unsigned long long a = keys[i], b = keys[ixj];
                bool sw = ((i & ks) == 0) ? (a < b) : (a > b);
                if (sw) { keys[i] = b; keys[ixj] = a; }
            }
        }
    __syncthreads();

    float accv = 0.f;
    for (int s = 0; s < 256; s++) {
        int mm = (int)(0xFFFFFFFFu - (unsigned)keys[s]);
        int t = stop[mm];
        accv += x1[(size_t)t * 512 + tid] + x2[(size_t)t * 512 + tid];
    }
    out[(size_t)p * 512 + tid] = accv * (0.5f / 256.0f);
}

// ---------------- launch ----------------
extern "C" void kernel_launch(void* const* d_in, const int* in_sizes, int n_in,
                              void* d_out, int out_size) {
    const float* clips = (const float*)d_in[0];
    const float* W     = (const float*)d_in[1];
    (void)in_sizes; (void)n_in; (void)out_size;

    k_init<<<1, 64>>>();
    k_scores<<<64, 1024>>>(clips, W);
    k_cross_mma<<<768, 256, SM_TOT>>>();
    k_select<<<96, 256>>>();
    k_rescue<<<48, 256>>>();
    k_intra<<<48, 512>>>((float*)d_out);
}

// round 14
// speedup vs baseline: 1.3199x; 1.1020x over previous
#include <cuda_runtime.h>
#include <cuda_bf16.h>
#include <cstdint>
#include <cmath>

#define EPS_F 1e-8f
#define TAU_CROSS 1e-4f

// ---------------- scratch (__device__ globals; no allocation allowed) ----------------
__device__ float g_proc[16777216];             // [64][512][512] gathered top-512 rows (fp32)
__device__ __nv_bfloat16 g_bhi[16777216];      // bf16 hi part of g_proc
__device__ __nv_bfloat16 g_blo[16777216];      // bf16 lo part (v - hi)
__device__ float g_rn2[32768];                 // [64][512] 1/||proc row||
__device__ unsigned long long g_t2[196608];    // [48*512][4 ct][2] per-tile top-2 keys
__device__ unsigned long long g_best[24576];   // winning key (low32 = 0xFFFFFFFF-m)
__device__ unsigned long long g_rlist[24576];  // flagged rows: n<<32|m1<<16|m2
__device__ int g_rcnt[48];

// ---------------- helpers ----------------
__device__ __forceinline__ unsigned int fsort(float f) {
    unsigned int u = __float_as_uint(f);
    return u ^ ((unsigned int)((int)u >> 31) | 0x80000000u);
}
__device__ __forceinline__ float finv(unsigned int u) {
    return __uint_as_float((u & 0x80000000u) ? (u ^ 0x80000000u) : ~u);
}
__device__ __forceinline__ void top2_upd(unsigned long long &b1, unsigned long long &b2,
                                         unsigned long long k) {
    if (k > b1) { b2 = b1; b1 = k; }
    else if (k > b2) b2 = k;
}
__device__ __forceinline__ void top2_merge(unsigned long long &b1, unsigned long long &b2,
                                           unsigned long long q1, unsigned long long q2) {
    unsigned long long hi = b1 > q1 ? b1 : q1;
    unsigned long long lo = b1 > q1 ? q1 : b1;
    unsigned long long m2 = b2 > q2 ? b2 : q2;
    b1 = hi;
    b2 = lo > m2 ? lo : m2;
}
__device__ __forceinline__ uint32_t smem_to_u32(const void* p) {
    uint32_t a;
    asm("{ .reg .u64 t; cvta.to.shared.u64 t, %1; cvt.u32.u64 %0, t; }" : "=r"(a) : "l"(p));
    return a;
}
__device__ __forceinline__ void cp16(uint32_t s, const void* g) {
    asm volatile("cp.async.cg.shared.global [%0], [%1], 16;" :: "r"(s), "l"(g));
}
#define CP_COMMIT() asm volatile("cp.async.commit_group;" ::: "memory")
#define CP_WAIT(N) asm volatile("cp.async.wait_group %0;" :: "n"(N) : "memory")

__device__ __forceinline__ void ldm_x4(uint32_t &r0, uint32_t &r1, uint32_t &r2, uint32_t &r3,
                                       uint32_t a) {
    asm volatile("ldmatrix.sync.aligned.m8n8.x4.shared.b16 {%0,%1,%2,%3}, [%4];"
                 : "=r"(r0), "=r"(r1), "=r"(r2), "=r"(r3) : "r"(a));
}
__device__ __forceinline__ void ldm_x2(uint32_t &r0, uint32_t &r1, uint32_t a) {
    asm volatile("ldmatrix.sync.aligned.m8n8.x2.shared.b16 {%0,%1}, [%2];"
                 : "=r"(r0), "=r"(r1) : "r"(a));
}
__device__ __forceinline__ void mma_bf16(float* d, const uint32_t* a, const uint32_t* b) {
    asm volatile("mma.sync.aligned.m16n8k16.row.col.f32.bf16.bf16.f32 "
                 "{%0,%1,%2,%3}, {%4,%5,%6,%7}, {%8,%9}, {%0,%1,%2,%3};"
                 : "+f"(d[0]), "+f"(d[1]), "+f"(d[2]), "+f"(d[3])
                 : "r"(a[0]), "r"(a[1]), "r"(a[2]), "r"(a[3]), "r"(b[0]), "r"(b[1]));
}

// ---------------- K init ----------------
__global__ void k_init() {
    int i = blockIdx.x * blockDim.x + threadIdx.x;
    if (i < 48) g_rcnt[i] = 0;
}

// ---------------- K0: scores -> fp32-quantized softmax weights -> top-512 -> gather ----
__global__ void __launch_bounds__(1024) k_scores(const float* __restrict__ clips,
                                                 const float* __restrict__ W) {
    __shared__ float sW[512];
    __shared__ float sS[1024];
    __shared__ float redf[1024];
    __shared__ double redd[1024];
    __shared__ unsigned long long keys[1024];
    __shared__ int sidx[512];
    __shared__ float snorm[512];
    int tid = threadIdx.x;
    int cb = blockIdx.x;
    const float* x = clips + (size_t)cb * (1024 * 512);
    if (tid < 512) { sW[tid] = W[tid]; snorm[tid] = 0.f; }
    __syncthreads();

    int warp = tid >> 5, lane = tid & 31;
    for (int tt = 0; tt < 32; tt++) {
        int token = (warp << 5) + tt;
        const float* r = x + (size_t)token * 512;
        float s = 0.f;
#pragma unroll 4
        for (int d = lane; d < 512; d += 32) s += r[d] * sW[d];
#pragma unroll
        for (int o = 16; o; o >>= 1) s += __shfl_xor_sync(0xFFFFFFFFu, s, o);
        if (lane == 0) sS[token] = s;
    }
    __syncthreads();

    redf[tid] = sS[tid];
    __syncthreads();
    for (int sft = 512; sft; sft >>= 1) {
        if (tid < sft) redf[tid] = fmaxf(redf[tid], redf[tid + sft]);
        __syncthreads();
    }
    float smax = redf[0];

    double e = exp((double)sS[tid] - (double)smax);
    redd[tid] = e;
    __syncthreads();
    for (int sft = 512; sft; sft >>= 1) {
        if (tid < sft) redd[tid] += redd[tid + sft];
        __syncthreads();
    }
    double esum = redd[0];

    float w32 = (float)(e / esum);  // fp32 weight XLA ranks by
    keys[tid] = ((unsigned long long)fsort(w32) << 32) |
                (unsigned long long)(tid ^ 0x3FF);  // tie -> lower index first
    __syncthreads();

    for (int ks = 2; ks <= 1024; ks <<= 1)
        for (int j = ks >> 1; j > 0; j >>= 1) {
            __syncthreads();
            int i = tid, ixj = i ^ j;
            if (ixj > i) {
                unsigned long long a = keys[i], b = keys[ixj];
                bool sw = ((i & ks) == 0) ? (a < b) : (a > b);
                if (sw) { keys[i] = b; keys[ixj] = a; }
            }
        }
    __syncthreads();
    if (tid < 512) sidx[tid] = ((int)(keys[tid] & 0x3FFu)) ^ 0x3FF;
    __syncthreads();

    // gather + row sumsq + bf16 hi/lo split
    float* dst = g_proc + (size_t)cb * 262144;
    __nv_bfloat16* dh = g_bhi + (size_t)cb * 262144;
    __nv_bfloat16* dl = g_blo + (size_t)cb * 262144;
    int half = tid >> 9;
    int d = tid & 511;
    for (int base = 0; base < 512; base += 2) {
        int j = base + half;
        float v = x[(size_t)sidx[j] * 512 + d];
        size_t o = (size_t)j * 512 + d;
        dst[o] = v;
        __nv_bfloat16 h = __float2bfloat16(v);
        dh[o] = h;
        dl[o] = __float2bfloat16(v - __bfloat162float(h));
        float p = v * v;
#pragma unroll
        for (int oo = 16; oo; oo >>= 1) p += __shfl_xor_sync(0xFFFFFFFFu, p, oo);
        if (lane == 0) atomicAdd(&snorm[j], p);
    }
    __syncthreads();
    if (tid < 512) g_rn2[(size_t)cb * 512 + tid] = 1.0f / sqrtf(snorm[tid]);
}

// ---------------- K2: mma.sync split-bf16 GEMM (hh+hl+lh) + fused per-tile TOP-2 ------
// 768 CTAs = 48 pairs * 4 rt * 4 ct; 128x128 tile; 8 warps, warp tile 64x32.
// K chunks of 16, DOUBLE-buffered. ROWB=48 (multiple of 16 -> ldmatrix alignment OK;
// banks 12r mod 32 distinct per 8-row group -> conflict-free).
// smem: 2 stages * 24576 = 49152 = entire 48KB default; sT2 ALIASES stage 0 (dead
// after the mainloop's final barrier).
#define ROWB 48
#define MAT_SZ 6144                  // 128 rows * 48 B
#define STAGE_BYTES 24576            // 4 matrices
#define OFF_AHI 0
#define OFF_ALO 6144
#define OFF_BHI 12288
#define OFF_BLO 18432
#define SM_T2 0                      // alias onto stage 0 (8192 B needed)
#define SM_TOT 49152

__global__ void __launch_bounds__(256, 2) k_cross_mma() {
    extern __shared__ __align__(16) char smem[];
    uint32_t sb = smem_to_u32(smem);
    int tid = threadIdx.x;
    int lane = tid & 31, wid = tid >> 5;
    int tile = blockIdx.x;
    int pair = tile >> 4;
    int rt = (tile >> 2) & 3;
    int ct = tile & 3;

    size_t abase = ((size_t)pair * 512 + rt * 128) * 512;        // x1 tile (A, rows n)
    size_t bbase = ((size_t)(pair + 16) * 512 + ct * 128) * 512; // x2 tile (B, cols m)

    // cp.async geometry: thread t covers (row = t>>1, 16B quad q = t&1) of each matrix
    int lrow = tid >> 1;
    int lq = tid & 1;
    uint32_t sdst = lrow * ROWB + lq * 16;
    size_t ga = abase + (size_t)lrow * 512 + lq * 8;  // elements (chunk adds c*16)
    size_t gb = bbase + (size_t)lrow * 512 + lq * 8;

    // fragment geometry (identical lane->addr maps as the passing R11 kernel)
    int wm = (wid & 1) * 64;
    int wn = (wid >> 1) * 32;
    uint32_t a_off = (uint32_t)((wm + (lane & 15)) * ROWB + ((lane & 16) ? 16 : 0));
    uint32_t b_off = (uint32_t)((wn + (lane & 7)) * ROWB + ((lane & 8) ? 16 : 0));

    float d[4][4][4];
#pragma unroll
    for (int i = 0; i < 4; i++)
#pragma unroll
        for (int j = 0; j < 4; j++)
#pragma unroll
            for (int r = 0; r < 4; r++) d[i][j][r] = 0.f;

    // issue chunk c (K columns c*16 .. c*16+15) into stage st
    auto issue = [&](int c, int st) {
        uint32_t s0 = sb + st * STAGE_BYTES + sdst;
        size_t go = (size_t)c * 16;
        cp16(s0 + OFF_AHI, g_bhi + ga + go);
        cp16(s0 + OFF_ALO, g_blo + ga + go);
        cp16(s0 + OFF_BHI, g_bhi + gb + go);
        cp16(s0 + OFF_BLO, g_blo + gb + go);
        CP_COMMIT();
    };

    issue(0, 0);
    for (int c = 0; c < 32; c++) {
        int st = c & 1;
        if (c + 1 < 32) {
            issue(c + 1, st ^ 1);
            CP_WAIT(1);
        } else {
            CP_WAIT(0);
        }
        __syncthreads();
        uint32_t stage = sb + st * STAGE_BYTES;
        uint32_t ah[4][4], al[4][4], bh[4][2], bl[4][2];
#pragma unroll
        for (int i = 0; i < 4; i++) {
            ldm_x4(ah[i][0], ah[i][1], ah[i][2], ah[i][3],
                   stage + OFF_AHI + a_off + i * (16 * ROWB));
            ldm_x4(al[i][0], al[i][1], al[i][2], al[i][3],
                   stage + OFF_ALO + a_off + i * (16 * ROWB));
        }
#pragma unroll
        for (int j = 0; j < 4; j++) {
            ldm_x2(bh[j][0], bh[j][1], stage + OFF_BHI + b_off + j * (8 * ROWB));
            ldm_x2(bl[j][0], bl[j][1], stage + OFF_BLO + b_off + j * (8 * ROWB));
        }
#pragma unroll
        for (int i = 0; i < 4; i++)
#pragma unroll
            for (int j = 0; j < 4; j++) {
                mma_bf16(d[i][j], ah[i], bh[j]);
                mma_bf16(d[i][j], ah[i], bl[j]);
                mma_bf16(d[i][j], al[i], bh[j]);
            }
        __syncthreads();  // stage st may be overwritten by issue() in iteration c+1
    }
    // mainloop done; stages are dead -> sT2 may alias stage 0 from here on.

    // epilogue: per-row TOP-2. D frag: c0=(r,c) c1=(r,c+1) c2=(r+8,c) c3=(r+8,c+1)
    const float* gRn = g_rn2 + (size_t)(pair + 16) * 512 + ct * 128;
    unsigned long long* sT2 = (unsigned long long*)(smem + SM_T2);
#pragma unroll
    for (int i = 0; i < 4; i++)
#pragma unroll
        for (int hf = 0; hf < 2; hf++) {
            int row = wm + i * 16 + hf * 8 + (lane >> 2);
            unsigned long long b1 = 0ull, b2 = 0ull;
#pragma unroll
            for (int j = 0; j < 4; j++) {
                int col = wn + j * 8 + (lane & 3) * 2;
                float v0 = d[i][j][hf * 2 + 0] * __ldg(gRn + col);
                float v1 = d[i][j][hf * 2 + 1] * __ldg(gRn + col + 1);
                top2_upd(b1, b2, ((unsigned long long)fsort(v0) << 32) |
                                 (unsigned long long)(0xFFFFFFFFu - (unsigned)(ct * 128 + col)));
                top2_upd(b1, b2, ((unsigned long long)fsort(v1) << 32) |
                                 (unsigned long long)(0xFFFFFFFFu - (unsigned)(ct * 128 + col + 1)));
            }
#pragma unroll
            for (int o = 1; o <= 2; o <<= 1) {
                unsigned long long q1 = __shfl_xor_sync(0xFFFFFFFFu, b1, o);
                unsigned long long q2 = __shfl_xor_sync(0xFFFFFFFFu, b2, o);
                top2_merge(b1, b2, q1, q2);
            }
            if ((lane & 3) == 0) {
                sT2[(row * 4 + (wid >> 1)) * 2] = b1;
                sT2[(row * 4 + (wid >> 1)) * 2 + 1] = b2;
            }
        }
    __syncthreads();
    if (tid < 128) {
        unsigned long long b1 = 0ull, b2 = 0ull;
#pragma unroll
        for (int nw = 0; nw < 4; nw++)
            top2_merge(b1, b2, sT2[(tid * 4 + nw) * 2], sT2[(tid * 4 + nw) * 2 + 1]);
        size_t base = (((size_t)pair * 512 + rt * 128 + tid) * 4 + ct) * 2;
        g_t2[base] = b1;
        g_t2[base + 1] = b2;
    }
}

// ---------------- K2b: global top-2 per row; flag near-ties ----------------
__global__ void k_select() {
    int row = blockIdx.x * 256 + threadIdx.x;  // < 24576
    int pair = row >> 9;
    unsigned long long b1 = 0ull, b2 = 0ull;
#pragma unroll
    for (int ct = 0; ct < 4; ct++) {
        size_t base = ((size_t)row * 4 + ct) * 2;
        top2_merge(b1, b2, g_t2[base], g_t2[base + 1]);
    }
    g_best[row] = b1;
    float v1 = finv((unsigned)(b1 >> 32));
    float v2 = finv((unsigned)(b2 >> 32));
    if (v1 - v2 < TAU_CROSS) {
        int n = row & 511;
        unsigned m1 = ~(unsigned)b1 & 0xFFFFu;
        unsigned m2 = ~(unsigned)b2 & 0xFFFFu;
        int slot = atomicAdd(&g_rcnt[pair], 1);
        g_rlist[(size_t)pair * 512 + slot] =
            ((unsigned long long)n << 32) | ((unsigned long long)m1 << 16) | m2;
    }
}

// ---------------- K2c: fp64 rescue of flagged rows (exact argmax) ----------------
__global__ void __launch_bounds__(256) k_rescue() {
    int pair = blockIdx.x;
    int w = threadIdx.x >> 5, lane = threadIdx.x & 31;
    int cnt = g_rcnt[pair];
    for (int e = w; e < cnt; e += 8) {
        unsigned long long ent = g_rlist[(size_t)pair * 512 + e];
        int n = (int)(ent >> 32);
        int m1 = (int)((ent >> 16) & 0xFFFFu);
        int m2 = (int)(ent & 0xFFFFu);
        const float* a = g_proc + (size_t)pair * 262144 + (size_t)n * 512;
        const float* p1 = g_proc + (size_t)(pair + 16) * 262144 + (size_t)m1 * 512;
        const float* p2 = g_proc + (size_t)(pair + 16) * 262144 + (size_t)m2 * 512;
        double d1 = 0, d2 = 0, q1 = 0, q2 = 0;
        for (int d = lane; d < 512; d += 32) {
            double av = a[d], v1 = p1[d], v2 = p2[d];
            d1 += av * v1; q1 += v1 * v1;
            d2 += av * v2; q2 += v2 * v2;
        }
#pragma unroll
        for (int o = 16; o; o >>= 1) {
            d1 += __shfl_xor_sync(0xFFFFFFFFu, d1, o);
            d2 += __shfl_xor_sync(0xFFFFFFFFu, d2, o);
            q1 += __shfl_xor_sync(0xFFFFFFFFu, q1, o);
            q2 += __shfl_xor_sync(0xFFFFFFFFu, q2, o);
        }
        if (lane == 0) {
            double s1 = d1 * sqrt(q2);
            double s2 = d2 * sqrt(q1);
            int m;
            if (s1 > s2) m = m1;
            else if (s2 > s1) m = m2;
            else m = m1 < m2 ? m1 : m2;
            g_best[(size_t)pair * 512 + n] =
                (0x8000000000000000ull) | (unsigned long long)(0xFFFFFFFFu - (unsigned)m);
        }
    }
}

// ---------------- K3: intra merge (row-0 sims, top-256 set, mean) + output ----------------
__global__ void __launch_bounds__(512) k_intra(float* __restrict__ out) {
    int p = blockIdx.x;
    const float* x1 = g_proc + (size_t)p * 262144;
    const float* x2 = g_proc + (size_t)(p + 16) * 262144;
    __shared__ float pm0[512];
    __shared__ float cdot[512];
    __shared__ float cn[512];
    __shared__ int stop[512];
    __shared__ unsigned long long keys[512];
    int tid = threadIdx.x;

    stop[tid] = (int)(0xFFFFFFFFu - (unsigned)g_best[(size_t)p * 512 + tid]);
    __syncthreads();
    int t0 = stop[0];
    pm0[tid] = 0.5f * (x1[(size_t)t0 * 512 + tid] + x2[(size_t)t0 * 512 + tid]);
    __syncthreads();

    int warp = tid >> 5, lane = tid & 31;
    for (int j = warp; j < 512; j += 16) {
        const float* r1 = x1 + (size_t)j * 512;
        const float* r2 = x2 + (size_t)j * 512;
        float sd = 0.f, sn = 0.f;
#pragma unroll 4
        for (int d = lane; d < 512; d += 32) {
            float v = 0.5f * (r1[d] + r2[d]);
            sd += pm0[d] * v;
            sn += v * v;
        }
#pragma unroll
        for (int o = 16; o; o >>= 1) {
            sd += __shfl_xor_sync(0xFFFFFFFFu, sd, o);
            sn += __shfl_xor_sync(0xFFFFFFFFu, sn, o);
        }
        if (lane == 0) { cdot[j] = sd; cn[j] = sqrtf(sn); }
    }
    __syncthreads();

    float n0 = cn[t0];
    {
        int t = stop[tid];
        float v = cdot[t] / fmaxf(n0 * cn[t], EPS_F);
        keys[tid] = ((unsigned long long)fsort(v) << 32) |
                    (unsigned long long)(0xFFFFFFFFu - (unsigned)tid);
    }

    for (int ks = 2; ks <= 512; ks <<= 1)
        for (int j = ks >> 1; j > 0; j >>= 1) {
            __syncthreads();
            int i = tid, ixj = i ^ j;
            if (ixj > i) {
                unsigned long long a = keys[i], b = keys[ixj];
                bool sw = ((i & ks) == 0) ? (a < b) : (a > b);
                if (sw) { keys[i] = b; keys[ixj] = a; }
            }
        }
    __syncthreads();

    float accv = 0.f;
    for (int s = 0; s < 256; s++) {
        int mm = (int)(0xFFFFFFFFu - (unsigned)keys[s]);
        int t = stop[mm];
        accv += x1[(size_t)t * 512 + tid] + x2[(size_t)t * 512 + tid];
    }
    out[(size_t)p * 512 + tid] = accv * (0.5f / 256.0f);
}

// ---------------- launch ----------------
extern "C" void kernel_launch(void* const* d_in, const int* in_sizes, int n_in,
                              void* d_out, int out_size) {
    const float* clips = (const float*)d_in[0];
    const float* W     = (const float*)d_in[1];
    (void)in_sizes; (void)n_in; (void)out_size;

    k_init<<<1, 64>>>();
    k_scores<<<64, 1024>>>(clips, W);
    k_cross_mma<<<768, 256, SM_TOT>>>();
    k_select<<<96, 256>>>();
    k_rescue<<<48, 256>>>();
    k_intra<<<48, 512>>>((float*)d_out);
}

// round 17
// speedup vs baseline: 1.3816x; 1.0468x over previous
#include <cuda_runtime.h>
#include <cuda_fp16.h>
#include <cstdint>
#include <cmath>

#define EPS_F 1e-8f
#define TAU_CROSS 1e-3f   // ~57 sigma of fp16 GEMM sim noise (sigma ~ 1.8e-5)

// ---------------- scratch (__device__ globals; no allocation allowed) ----------------
__device__ float g_proc[16777216];             // [64][512][512] gathered top-512 rows (fp32)
__device__ __half g_h16[16777216];             // fp16 of g_proc (GEMM operand)
__device__ float g_rn2[32768];                 // [64][512] 1/||proc row||
__device__ unsigned long long g_t2[294912];    // [48*512][4 ct][3] per-tile top-3 keys
__device__ unsigned long long g_best[24576];   // winning key (low32 = 0xFFFFFFFF-m)
__device__ unsigned long long g_rlist[24576];  // flagged rows: row index n
__device__ int g_rcnt[48];

// ---------------- helpers ----------------
__device__ __forceinline__ unsigned int fsort(float f) {
    unsigned int u = __float_as_uint(f);
    return u ^ ((unsigned int)((int)u >> 31) | 0x80000000u);
}
__device__ __forceinline__ float finv(unsigned int u) {
    return __uint_as_float((u & 0x80000000u) ? (u ^ 0x80000000u) : ~u);
}
__device__ __forceinline__ void top2_upd(unsigned long long &b1, unsigned long long &b2,
                                         unsigned long long k) {
    if (k > b1) { b2 = b1; b1 = k; }
    else if (k > b2) b2 = k;
}
__device__ __forceinline__ void top3_upd(unsigned long long &b1, unsigned long long &b2,
                                         unsigned long long &b3, unsigned long long k) {
    if (k > b1) { b3 = b2; b2 = b1; b1 = k; }
    else if (k > b2) { b3 = b2; b2 = k; }
    else if (k > b3) b3 = k;
}
__device__ __forceinline__ uint32_t smem_to_u32(const void* p) {
    uint32_t a;
    asm("{ .reg .u64 t; cvta.to.shared.u64 t, %1; cvt.u32.u64 %0, t; }" : "=r"(a) : "l"(p));
    return a;
}
__device__ __forceinline__ void cp16(uint32_t s, const void* g) {
    asm volatile("cp.async.cg.shared.global [%0], [%1], 16;" :: "r"(s), "l"(g));
}
#define CP_COMMIT() asm volatile("cp.async.commit_group;" ::: "memory")
#define CP_WAIT(N) asm volatile("cp.async.wait_group %0;" :: "n"(N) : "memory")

__device__ __forceinline__ void ldm_x4(uint32_t &r0, uint32_t &r1, uint32_t &r2, uint32_t &r3,
                                       uint32_t a) {
    asm volatile("ldmatrix.sync.aligned.m8n8.x4.shared.b16 {%0,%1,%2,%3}, [%4];"
                 : "=r"(r0), "=r"(r1), "=r"(r2), "=r"(r3) : "r"(a));
}
__device__ __forceinline__ void ldm_x2(uint32_t &r0, uint32_t &r1, uint32_t a) {
    asm volatile("ldmatrix.sync.aligned.m8n8.x2.shared.b16 {%0,%1}, [%2];"
                 : "=r"(r0), "=r"(r1) : "r"(a));
}
__device__ __forceinline__ void mma_f16(float* d, const uint32_t* a, const uint32_t* b) {
    asm volatile("mma.sync.aligned.m16n8k16.row.col.f32.f16.f16.f32 "
                 "{%0,%1,%2,%3}, {%4,%5,%6,%7}, {%8,%9}, {%0,%1,%2,%3};"
                 : "+f"(d[0]), "+f"(d[1]), "+f"(d[2]), "+f"(d[3])
                 : "r"(a[0]), "r"(a[1]), "r"(a[2]), "r"(a[3]), "r"(b[0]), "r"(b[1]));
}

// ---------------- K init ----------------
__global__ void k_init() {
    int i = blockIdx.x * blockDim.x + threadIdx.x;
    if (i < 48) g_rcnt[i] = 0;
}

// ---------------- K0: scores -> fp32-quantized softmax weights -> top-512 -> gather ----
__global__ void __launch_bounds__(1024) k_scores(const float* __restrict__ clips,
                                                 const float* __restrict__ W) {
    __shared__ float sW[512];
    __shared__ float sS[1024];
    __shared__ float redf[1024];
    __shared__ double redd[1024];
    __shared__ unsigned long long keys[1024];
    __shared__ int sidx[512];
    __shared__ float snorm[512];
    int tid = threadIdx.x;
    int cb = blockIdx.x;
    const float* x = clips + (size_t)cb * (1024 * 512);
    if (tid < 512) { sW[tid] = W[tid]; snorm[tid] = 0.f; }
    __syncthreads();

    int warp = tid >> 5, lane = tid & 31;
    for (int tt = 0; tt < 32; tt++) {
        int token = (warp << 5) + tt;
        const float* r = x + (size_t)token * 512;
        float s = 0.f;
#pragma unroll 4
        for (int d = lane; d < 512; d += 32) s += r[d] * sW[d];
#pragma unroll
        for (int o = 16; o; o >>= 1) s += __shfl_xor_sync(0xFFFFFFFFu, s, o);
        if (lane == 0) sS[token] = s;
    }
    __syncthreads();

    redf[tid] = sS[tid];
    __syncthreads();
    for (int sft = 512; sft; sft >>= 1) {
        if (tid < sft) redf[tid] = fmaxf(redf[tid], redf[tid + sft]);
        __syncthreads();
    }
    float smax = redf[0];

    double e = exp((double)sS[tid] - (double)smax);
    redd[tid] = e;
    __syncthreads();
    for (int sft = 512; sft; sft >>= 1) {
        if (tid < sft) redd[tid] += redd[tid + sft];
        __syncthreads();
    }
    double esum = redd[0];

    float w32 = (float)(e / esum);  // fp32 weight XLA ranks by
    keys[tid] = ((unsigned long long)fsort(w32) << 32) |
                (unsigned long long)(tid ^ 0x3FF);  // tie -> lower index first
    __syncthreads();

    for (int ks = 2; ks <= 1024; ks <<= 1)
        for (int j = ks >> 1; j > 0; j >>= 1) {
            __syncthreads();
            int i = tid, ixj = i ^ j;
            if (ixj > i) {
                unsigned long long a = keys[i], b = keys[ixj];
                bool sw = ((i & ks) == 0) ? (a < b) : (a > b);
                if (sw) { keys[i] = b; keys[ixj] = a; }
            }
        }
    __syncthreads();
    if (tid < 512) sidx[tid] = ((int)(keys[tid] & 0x3FFu)) ^ 0x3FF;
    __syncthreads();

    // gather + row sumsq + fp16 copy
    float* dst = g_proc + (size_t)cb * 262144;
    __half* dh = g_h16 + (size_t)cb * 262144;
    int half_ = tid >> 9;
    int d = tid & 511;
    for (int base = 0; base < 512; base += 2) {
        int j = base + half_;
        float v = x[(size_t)sidx[j] * 512 + d];
        size_t o = (size_t)j * 512 + d;
        dst[o] = v;
        dh[o] = __float2half_rn(v);
        float p = v * v;
#pragma unroll
        for (int oo = 16; oo; oo >>= 1) p += __shfl_xor_sync(0xFFFFFFFFu, p, oo);
        if (lane == 0) atomicAdd(&snorm[j], p);
    }
    __syncthreads();
    if (tid < 512) g_rn2[(size_t)cb * 512 + tid] = 1.0f / sqrtf(snorm[tid]);
}

// ---------------- K2: plain-fp16 mma.sync GEMM + fused per-tile TOP-3 ----------------
// 768 CTAs = 48 pairs * 4 rt * 4 ct; 128x128 tile; 8 warps, warp tile 64x32.
// K chunks of 32, ROWB=80 (R11-proven alignment/banks), DOUBLE-buffered (2 matrices).
// smem: 2 stages * 20480 = 40960; sT2 aliases stage 0 (dead after mainloop).
#define ROWB 80
#define MAT_SZ 10240                 // 128 rows * 80 B
#define STAGE_BYTES 20480            // 2 matrices (A, B)
#define OFF_A 0
#define OFF_B 10240
#define SM_T2 0                      // alias onto stage 0 (needs 12288 B <= 20480)
#define SM_TOT 40960

__global__ void __launch_bounds__(256, 2) k_cross_mma() {
    extern __shared__ __align__(16) char smem[];
    uint32_t sb = smem_to_u32(smem);
    int tid = threadIdx.x;
    int lane = tid & 31, wid = tid >> 5;
    int tile = blockIdx.x;
    int pair = tile >> 4;
    int rt = (tile >> 2) & 3;
    int ct = tile & 3;

    size_t abase = ((size_t)pair * 512 + rt * 128) * 512;        // x1 tile (A, rows n)
    size_t bbase = ((size_t)(pair + 16) * 512 + ct * 128) * 512; // x2 tile (B, cols m)

    // cp.async geometry (R11-proven): thread t covers row=t>>1, quads (t&1)*2+{0,1}
    int lrow = tid >> 1;
    int lq = (tid & 1) * 2;
    uint32_t sdst = lrow * ROWB + lq * 16;
    size_t ga = abase + (size_t)lrow * 512 + lq * 8;  // elements; chunk adds c*32
    size_t gb = bbase + (size_t)lrow * 512 + lq * 8;

    // fragment geometry (R11-proven lane->addr maps)
    int wm = (wid & 1) * 64;
    int wn = (wid >> 1) * 32;
    uint32_t a_off = (uint32_t)((wm + (lane & 15)) * ROWB + ((lane & 16) ? 16 : 0));
    uint32_t b_off = (uint32_t)((wn + (lane & 7)) * ROWB + ((lane & 8) ? 16 : 0));

    float d[4][4][4];
#pragma unroll
    for (int i = 0; i < 4; i++)
#pragma unroll
        for (int j = 0; j < 4; j++)
#pragma unroll
            for (int r = 0; r < 4; r++) d[i][j][r] = 0.f;

    auto issue = [&](int c, int st) {
        uint32_t s0 = sb + st * STAGE_BYTES + sdst;
        size_t go = (size_t)c * 32;
        cp16(s0 + OFF_A, g_h16 + ga + go);
        cp16(s0 + OFF_A + 16, g_h16 + ga + go + 8);
        cp16(s0 + OFF_B, g_h16 + gb + go);
        cp16(s0 + OFF_B + 16, g_h16 + gb + go + 8);
        CP_COMMIT();
    };

    issue(0, 0);
    for (int c = 0; c < 16; c++) {
        int st = c & 1;
        if (c + 1 < 16) {
            issue(c + 1, st ^ 1);
            CP_WAIT(1);
        } else {
            CP_WAIT(0);
        }
        __syncthreads();
        uint32_t stage = sb + st * STAGE_BYTES;
#pragma unroll
        for (int s = 0; s < 2; s++) {
            uint32_t ah[4][4], bh[4][2];
#pragma unroll
            for (int i = 0; i < 4; i++)
                ldm_x4(ah[i][0], ah[i][1], ah[i][2], ah[i][3],
                       stage + OFF_A + a_off + i * (16 * ROWB) + s * 32);
#pragma unroll
            for (int j = 0; j < 4; j++)
                ldm_x2(bh[j][0], bh[j][1], stage + OFF_B + b_off + j * (8 * ROWB) + s * 32);
#pragma unroll
            for (int i = 0; i < 4; i++)
#pragma unroll
                for (int j = 0; j < 4; j++) mma_f16(d[i][j], ah[i], bh[j]);
        }
        __syncthreads();  // stage st may be overwritten by issue() next iteration
    }
    // stages dead from here; sT2 aliases stage 0.

    // epilogue: per-row TOP-3 within this 128-col tile
    const float* gRn = g_rn2 + (size_t)(pair + 16) * 512 + ct * 128;
    unsigned long long* sT2 = (unsigned long long*)(smem + SM_T2);
#pragma unroll
    for (int i = 0; i < 4; i++)
#pragma unroll
        for (int hf = 0; hf < 2; hf++) {
            int row = wm + i * 16 + hf * 8 + (lane >> 2);
            unsigned long long b1 = 0ull, b2 = 0ull, b3 = 0ull;
#pragma unroll
            for (int j = 0; j < 4; j++) {
                int col = wn + j * 8 + (lane & 3) * 2;
                float v0 = d[i][j][hf * 2 + 0] * __ldg(gRn + col);
                float v1 = d[i][j][hf * 2 + 1] * __ldg(gRn + col + 1);
                top3_upd(b1, b2, b3, ((unsigned long long)fsort(v0) << 32) |
                                     (unsigned long long)(0xFFFFFFFFu - (unsigned)(ct * 128 + col)));
                top3_upd(b1, b2, b3, ((unsigned long long)fsort(v1) << 32) |
                                     (unsigned long long)(0xFFFFFFFFu - (unsigned)(ct * 128 + col + 1)));
            }
#pragma unroll
            for (int o = 1; o <= 2; o <<= 1) {
                unsigned long long q1 = __shfl_xor_sync(0xFFFFFFFFu, b1, o);
                unsigned long long q2 = __shfl_xor_sync(0xFFFFFFFFu, b2, o);
                unsigned long long q3 = __shfl_xor_sync(0xFFFFFFFFu, b3, o);
                top3_upd(b1, b2, b3, q1);
                top3_upd(b1, b2, b3, q2);
                top3_upd(b1, b2, b3, q3);
            }
            if ((lane & 3) == 0) {
                int nw = wid >> 1;
                sT2[(row * 4 + nw) * 3 + 0] = b1;
                sT2[(row * 4 + nw) * 3 + 1] = b2;
                sT2[(row * 4 + nw) * 3 + 2] = b3;
            }
        }
    __syncthreads();
    if (tid < 128) {
        unsigned long long b1 = 0ull, b2 = 0ull, b3 = 0ull;
#pragma unroll
        for (int nw = 0; nw < 4; nw++)
#pragma unroll
            for (int k = 0; k < 3; k++) top3_upd(b1, b2, b3, sT2[(tid * 4 + nw) * 3 + k]);
        size_t base = (((size_t)pair * 512 + rt * 128 + tid) * 4 + ct) * 3;
        g_t2[base] = b1;
        g_t2[base + 1] = b2;
        g_t2[base + 2] = b3;
    }
}

// ---------------- K2b: global top-2 over 12 candidates; flag near-ties ----------------
__global__ void k_select() {
    int row = blockIdx.x * 256 + threadIdx.x;  // < 24576
    int pair = row >> 9;
    unsigned long long b1 = 0ull, b2 = 0ull;
#pragma unroll
    for (int ct = 0; ct < 4; ct++) {
        size_t base = ((size_t)row * 4 + ct) * 3;
#pragma unroll
        for (int k = 0; k < 3; k++) top2_upd(b1, b2, g_t2[base + k]);
    }
    g_best[row] = b1;
    float v1 = finv((unsigned)(b1 >> 32));
    float v2 = finv((unsigned)(b2 >> 32));
    if (v1 - v2 < TAU_CROSS) {
        int slot = atomicAdd(&g_rcnt[pair], 1);
        g_rlist[(size_t)pair * 512 + slot] = (unsigned long long)(row & 511);
    }
}

// ---------------- K2c: rescue — fp32 exact over 12 candidates, fp64 duel on top-2 ------
__global__ void __launch_bounds__(256) k_rescue() {
    int pair = blockIdx.x;
    int w = threadIdx.x >> 5, lane = threadIdx.x & 31;
    int cnt = g_rcnt[pair];
    const float* rnb = g_rn2 + (size_t)(pair + 16) * 512;
    for (int e = w; e < cnt; e += 8) {
        int n = (int)g_rlist[(size_t)pair * 512 + e];
        const float* a = g_proc + (size_t)pair * 262144 + (size_t)n * 512;
        int ms[12];
        size_t tbase = ((size_t)(pair * 512 + n)) * 4 * 3;
#pragma unroll
        for (int t = 0; t < 12; t++)
            ms[t] = (int)((0xFFFFFFFFu - (unsigned)g_t2[tbase + t]) & 0xFFFFu);
        unsigned long long b1 = 0ull, b2 = 0ull;
#pragma unroll
        for (int t = 0; t < 12; t++) {
            const float* p = g_proc + (size_t)(pair + 16) * 262144 + (size_t)ms[t] * 512;
            float s = 0.f;
#pragma unroll 4
            for (int dd = lane; dd < 512; dd += 32) s += a[dd] * p[dd];
#pragma unroll
            for (int o = 16; o; o >>= 1) s += __shfl_xor_sync(0xFFFFFFFFu, s, o);
            if (lane == 0) {
                float v = s * rnb[ms[t]];
                top2_upd(b1, b2, ((unsigned long long)fsort(v) << 32) |
                                 (unsigned long long)(0xFFFFFFFFu - (unsigned)ms[t]));
            }
        }
        int m1 = (int)((0xFFFFFFFFu - (unsigned)__shfl_sync(0xFFFFFFFFu, b1, 0)) & 0xFFFFu);
        int m2 = (int)((0xFFFFFFFFu - (unsigned)__shfl_sync(0xFFFFFFFFu, b2, 0)) & 0xFFFFu);
        const float* p1 = g_proc + (size_t)(pair + 16) * 262144 + (size_t)m1 * 512;
        const float* p2 = g_proc + (size_t)(pair + 16) * 262144 + (size_t)m2 * 512;
        double d1 = 0, d2 = 0, q1 = 0, q2 = 0;
        for (int dd = lane; dd < 512; dd += 32) {
            double av = a[dd], v1 = p1[dd], v2 = p2[dd];
            d1 += av * v1; q1 += v1 * v1;
            d2 += av * v2; q2 += v2 * v2;
        }
#pragma unroll
        for (int o = 16; o; o >>= 1) {
            d1 += __shfl_xor_sync(0xFFFFFFFFu, d1, o);
            d2 += __shfl_xor_sync(0xFFFFFFFFu, d2, o);
            q1 += __shfl_xor_sync(0xFFFFFFFFu, q1, o);
            q2 += __shfl_xor_sync(0xFFFFFFFFu, q2, o);
        }
        if (lane == 0) {
            double s1 = d1 * sqrt(q2);
            double s2 = d2 * sqrt(q1);
            int m;
            if (s1 > s2) m = m1;
            else if (s2 > s1) m = m2;
            else m = m1 < m2 ? m1 : m2;
            g_best[(size_t)pair * 512 + n] =
                (0x8000000000000000ull) | (unsigned long long)(0xFFFFFFFFu - (unsigned)m);
        }
    }
}

// ---------------- K3: intra merge (row-0 sims, top-256 set, mean) + output ----------------
__global__ void __launch_bounds__(512) k_intra(float* __restrict__ out) {
    int p = blockIdx.x;
    const float* x1 = g_proc + (size_t)p * 262144;
    const float* x2 = g_proc + (size_t)(p + 16) * 262144;
    __shared__ float pm0[512];
    __shared__ float cdot[512];
    __shared__ float cn[512];
    __shared__ int stop[512];
    __shared__ unsigned long long keys[512];
    int tid = threadIdx.x;

    stop[tid] = (int)(0xFFFFFFFFu - (unsigned)g_best[(size_t)p * 512 + tid]);
    __syncthreads();
    int t0 = stop[0];
    pm0[tid] = 0.5f * (x1[(size_t)t0 * 512 + tid] + x2[(size_t)t0 * 512 + tid]);
    __syncthreads();

    int warp = tid >> 5, lane = tid & 31;
    for (int j = warp; j < 512; j += 16) {
        const float* r1 = x1 + (size_t)j * 512;
        const float* r2 = x2 + (size_t)j * 512;
        float sd = 0.f, sn = 0.f;
#pragma unroll 4
        for (int d = lane; d < 512; d += 32) {
            float v = 0.5f * (r1[d] + r2[d]);
            sd += pm0[d] * v;
            sn += v * v;
        }
#pragma unroll
        for (int o = 16; o; o >>= 1) {
            sd += __shfl_xor_sync(0xFFFFFFFFu, sd, o);
            sn += __shfl_xor_sync(0xFFFFFFFFu, sn, o);
        }
        if (lane == 0) { cdot[j] = sd; cn[j] = sqrtf(sn); }
    }
    __syncthreads();

    float n0 = cn[t0];
    {
        int t = stop[tid];
        float v = cdot[t] / fmaxf(n0 * cn[t], EPS_F);
        keys[tid] = ((unsigned long long)fsort(v) << 32) |
                    (unsigned long long)(0xFFFFFFFFu - (unsigned)tid);
    }

    for (int ks = 2; ks <= 512; ks <<= 1)
        for (int j = ks >> 1; j > 0; j >>= 1) {
            __syncthreads();
            int i = tid, ixj = i ^ j;
            if (ixj > i) {
                unsigned long long a = keys[i], b = keys[ixj];
                bool sw = ((i & ks) == 0) ? (a < b) : (a > b);
                if (sw) { keys[i] = b; keys[ixj] = a; }
            }
        }
    __syncthreads();

    float accv = 0.f;
    for (int s = 0; s < 256; s++) {
        int mm = (int)(0xFFFFFFFFu - (unsigned)keys[s]);
        int t = stop[mm];
        accv += x1[(size_t)t * 512 + tid] + x2[(size_t)t * 512 + tid];
    }
    out[(size_t)p * 512 + tid] = accv * (0.5f / 256.0f);
}

// ---------------- launch ----------------
extern "C" void kernel_launch(void* const* d_in, const int* in_sizes, int n_in,
                              void* d_out, int out_size) {
    const float* clips = (const float*)d_in[0];
    const float* W     = (const float*)d_in[1];
    (void)in_sizes; (void)n_in; (void)out_size;

    k_init<<<1, 64>>>();
    k_scores<<<64, 1024>>>(clips, W);
    k_cross_mma<<<768, 256, SM_TOT>>>();
    k_select<<<96, 256>>>();
    k_rescue<<<48, 256>>>();
    k_intra<<<48, 512>>>((float*)d_out);
}